// round 13
// baseline (speedup 1.0000x reference)
#include <cuda_runtime.h>
#include <cstdint>

#define TT 512
#define BB 64
#define EE 300
#define HH 512
#define LL 5
#define G3H 1536
#define NCTA 128

typedef unsigned long long u64;

// ---------------- static device scratch ----------------
__device__ float g_xp[(size_t)TT * BB * G3H];   // input projections (reused both layers)
__device__ float g_ys0[(size_t)TT * BB * HH];   // layer-0 outputs
__device__ float g_h[2][HH * BB];               // double-buffered recurrent state, k-major [H][B]
__device__ float g_pooled[TT * HH];
__device__ __align__(512) unsigned int g_flags[NCTA];   // per-CTA step flags (all equal at kernel boundaries)

// ---------------- packed f32x2 helpers ----------------
__device__ __forceinline__ void fma2(u64& d, u64 a, u64 b) {
    asm("fma.rn.f32x2 %0, %1, %2, %0;" : "+l"(d) : "l"(a), "l"(b));
}
__device__ __forceinline__ u64 pack2(float x, float y) {
    u64 v; asm("mov.b64 %0, {%1, %2};" : "=l"(v) : "f"(x), "f"(y)); return v;
}
__device__ __forceinline__ float2 unpack2(u64 v) {
    float2 r; asm("mov.b64 {%0, %1}, %2;" : "=f"(r.x), "=f"(r.y) : "l"(v)); return r;
}
__device__ __forceinline__ u64 add2(u64 a, u64 b) {
    u64 d; asm("add.rn.f32x2 %0, %1, %2;" : "=l"(d) : "l"(a), "l"(b)); return d;
}
__device__ __forceinline__ void ldcg_pair(const float* p, u64& a, u64& b) {
    asm volatile("ld.global.cg.v2.u64 {%0, %1}, [%2];" : "=l"(a), "=l"(b) : "l"(p));
}
__device__ __forceinline__ float ldg_f32(const float* p) {
    float v; asm volatile("ld.global.f32 %0, [%1];" : "=f"(v) : "l"(p)); return v;
}

// ---------------- flag barrier primitives ----------------
// Publish: (all h stores) -> __syncthreads() -> thread 0 does st.release of its slot.
__device__ __forceinline__ void flag_publish(unsigned gen) {
    if (threadIdx.x == 0) {
        asm volatile("st.release.gpu.global.u32 [%0], %1;"
                     :: "l"(g_flags + blockIdx.x), "r"(gen) : "memory");
    }
}
// Wait: warp 0 only; each lane acquires 4 flags; exits when all 128 >= target.
__device__ __forceinline__ void flag_wait_warp0(unsigned target) {
    const int lane = threadIdx.x & 31;
    const unsigned* f = g_flags + lane;
    for (;;) {
        unsigned v0, v1, v2, v3;
        asm volatile("ld.acquire.gpu.global.u32 %0, [%1];" : "=r"(v0) : "l"(f)       : "memory");
        asm volatile("ld.acquire.gpu.global.u32 %0, [%1];" : "=r"(v1) : "l"(f + 32)  : "memory");
        asm volatile("ld.acquire.gpu.global.u32 %0, [%1];" : "=r"(v2) : "l"(f + 64)  : "memory");
        asm volatile("ld.acquire.gpu.global.u32 %0, [%1];" : "=r"(v3) : "l"(f + 96)  : "memory");
        bool ok = ((int)(v0 - target) >= 0) & ((int)(v1 - target) >= 0) &
                  ((int)(v2 - target) >= 0) & ((int)(v3 - target) >= 0);
        if (__all_sync(0xffffffffu, ok)) break;
    }
}

// ---------------- SGEMM with bias (unchanged) ----------------
__global__ void __launch_bounds__(256) sgemm_bias_kernel(
    const float* __restrict__ Aemb, const int* __restrict__ idx,
    const float* __restrict__ W, const float* __restrict__ bias,
    int K, int gather)
{
    __shared__ float As[16][132];
    __shared__ u64   Bs[16][66];

    const int tid = threadIdx.x;
    const int m0 = blockIdx.y * 128;
    const int n0 = blockIdx.x * 64;

    const int arow_l = tid >> 1;
    const int ak8 = (tid & 1) * 8;
    const int m = m0 + arow_l;
    const float* arow;
    if (gather) arow = Aemb + (size_t)idx[m] * K;
    else        arow = g_ys0 + (size_t)m * K;

    const int brow_l = tid >> 2;
    const int bk4 = (tid & 3) * 4;
    const float* brow = W + (size_t)(n0 + brow_l) * K;

    const int tx = tid & 15;
    const int ty = tid >> 4;

    u64 c[4][4];
    #pragma unroll
    for (int i = 0; i < 4; i++)
        #pragma unroll
        for (int j = 0; j < 4; j++) c[i][j] = 0ull;

    for (int k0 = 0; k0 < K; k0 += 16) {
        float va[8];
        if (k0 + ak8 + 7 < K) {
            float4 v0 = *(const float4*)(arow + k0 + ak8);
            float4 v1 = *(const float4*)(arow + k0 + ak8 + 4);
            va[0]=v0.x; va[1]=v0.y; va[2]=v0.z; va[3]=v0.w;
            va[4]=v1.x; va[5]=v1.y; va[6]=v1.z; va[7]=v1.w;
        } else {
            #pragma unroll
            for (int i = 0; i < 8; i++) va[i] = (k0 + ak8 + i < K) ? arow[k0 + ak8 + i] : 0.f;
        }
        float vb[4];
        if (k0 + bk4 + 3 < K) {
            float4 v = *(const float4*)(brow + k0 + bk4);
            vb[0]=v.x; vb[1]=v.y; vb[2]=v.z; vb[3]=v.w;
        } else {
            #pragma unroll
            for (int i = 0; i < 4; i++) vb[i] = (k0 + bk4 + i < K) ? brow[k0 + bk4 + i] : 0.f;
        }
        __syncthreads();
        #pragma unroll
        for (int i = 0; i < 8; i++) As[ak8 + i][arow_l] = va[i];
        #pragma unroll
        for (int i = 0; i < 4; i++) Bs[bk4 + i][brow_l] = pack2(vb[i], vb[i]);
        __syncthreads();

        #pragma unroll
        for (int k = 0; k < 16; k++) {
            ulonglong2 a01 = *(const ulonglong2*)&As[k][ty * 8];
            ulonglong2 a23 = *(const ulonglong2*)&As[k][ty * 8 + 4];
            ulonglong2 b01 = *(const ulonglong2*)&Bs[k][tx * 4];
            ulonglong2 b23 = *(const ulonglong2*)&Bs[k][tx * 4 + 2];
            u64 a[4] = {a01.x, a01.y, a23.x, a23.y};
            u64 b[4] = {b01.x, b01.y, b23.x, b23.y};
            #pragma unroll
            for (int mp = 0; mp < 4; mp++)
                #pragma unroll
                for (int n = 0; n < 4; n++) fma2(c[mp][n], a[mp], b[n]);
        }
    }

    float4 bv = *(const float4*)(bias + n0 + tx * 4);
    #pragma unroll
    for (int mp = 0; mp < 4; mp++) {
        float2 v0 = unpack2(c[mp][0]);
        float2 v1 = unpack2(c[mp][1]);
        float2 v2 = unpack2(c[mp][2]);
        float2 v3 = unpack2(c[mp][3]);
        int mlo = m0 + ty * 8 + mp * 2;
        float4 lo = {v0.x + bv.x, v1.x + bv.y, v2.x + bv.z, v3.x + bv.w};
        float4 hi = {v0.y + bv.x, v1.y + bv.y, v2.y + bv.z, v3.y + bv.w};
        *(float4*)(g_xp + (size_t)mlo * G3H + n0 + tx * 4) = lo;
        *(float4*)(g_xp + (size_t)(mlo + 1) * G3H + n0 + tx * 4) = hi;
    }
}

// ---------------- persistent GRU layer kernel (v3: flag barrier, depth-3 prefetch) ----------------
#define W_SMEM_F   (HH * 12)          // 6144 floats
#define RED_SMEM_F (8 * 12 * 64)      // 6144 floats
#define GRU_SMEM_BYTES ((W_SMEM_F + RED_SMEM_F + 256) * 4)   // 50176 B

__global__ void __launch_bounds__(256, 1) gru_layer_kernel(
    const float* __restrict__ Whh, const float* __restrict__ bhh, int phase)
{
    extern __shared__ float smem_dyn[];
    float* w_s    = smem_dyn;                 // [k:512][r:12], r = g*4 + jj
    float* red_s  = w_s + W_SMEM_F;           // [warp:8][r:12][batch:64]
    float* pool_s = red_s + RED_SMEM_F;       // [256]

    const int tid = threadIdx.x;
    const int j0 = blockIdx.x * 4;

    // invariant: all flags equal at kernel entry; own slot gives the base.
    const unsigned base = g_flags[blockIdx.x];

    // stage Whh slice (coalesced)
    for (int i = tid; i < HH * 12; i += 256) {
        int r = i >> 9, k = i & 511;          // r = g*4 + jj
        int g = r >> 2, jj = r & 3;
        w_s[k * 12 + r] = Whh[(size_t)(g * HH + j0 + jj) * HH + k];
    }
    // zero h buffer 0 (this CTA's 4 columns)
    g_h[0][blockIdx.x * 256 + tid] = 0.f;

    const int w    = tid >> 5;
    const int lane = tid & 31;
    const int kpar = lane >> 4;
    const int b4   = (lane & 15) * 4;
    const int eb   = tid >> 2;
    const int jj   = tid & 3;
    const int col  = j0 + jj;

    const float bhr = bhh[col], bhz = bhh[HH + col], bhn = bhh[2 * HH + col];
    float h_prev = 0.f;

    const float* wk_base = w_s + (w * 64 + kpar) * 12;
    const size_t h_off   = (size_t)(w * 64 + kpar) * BB + b4;

    // prefetch xp for t=0 (independent of barrier)
    const float* xrow0 = g_xp + (size_t)eb * G3H + col;
    float xr = ldg_f32(xrow0);
    float xz = ldg_f32(xrow0 + HH);
    float xn = ldg_f32(xrow0 + 2 * HH);

    // init barrier
    __syncthreads();
    flag_publish(base + 1);
    if (w == 0) flag_wait_warp0(base + 1);
    __syncthreads();

    for (int t = 0; t < TT; ++t) {
        const float* hp = g_h[t & 1] + h_off;

        u64 acc[12][2];
        #pragma unroll
        for (int r = 0; r < 12; ++r) { acc[r][0] = 0ull; acc[r][1] = 0ull; }

        // depth-3 pipelined GEMV over 32 iterations (2 k each)
        u64 hb[4][2];
        ldcg_pair(hp,       hb[0][0], hb[0][1]);
        ldcg_pair(hp + 128, hb[1][0], hb[1][1]);
        ldcg_pair(hp + 256, hb[2][0], hb[2][1]);
        float4 wA0 = *(const float4*)(wk_base);
        float4 wA1 = *(const float4*)(wk_base + 4);
        float4 wA2 = *(const float4*)(wk_base + 8);

        #pragma unroll 4
        for (int i = 0; i < 32; ++i) {
            if (i + 3 < 32)
                ldcg_pair(hp + (size_t)(i + 3) * 128, hb[(i + 3) & 3][0], hb[(i + 3) & 3][1]);
            float4 wB0, wB1, wB2;
            if (i + 1 < 32) {
                const float* wn = wk_base + (i + 1) * 24;
                wB0 = *(const float4*)(wn);
                wB1 = *(const float4*)(wn + 4);
                wB2 = *(const float4*)(wn + 8);
            }
            u64 h0 = hb[i & 3][0], h1 = hb[i & 3][1];
            float wf[12] = {wA0.x, wA0.y, wA0.z, wA0.w,
                            wA1.x, wA1.y, wA1.z, wA1.w,
                            wA2.x, wA2.y, wA2.z, wA2.w};
            #pragma unroll
            for (int r = 0; r < 12; ++r) {
                u64 wp = pack2(wf[r], wf[r]);
                fma2(acc[r][0], h0, wp);
                fma2(acc[r][1], h1, wp);
            }
            wA0 = wB0; wA1 = wB1; wA2 = wB2;
        }

        // fold odd-k half into even half
        #pragma unroll
        for (int r = 0; r < 12; ++r) {
            u64 o0 = __shfl_down_sync(0xffffffffu, acc[r][0], 16);
            u64 o1 = __shfl_down_sync(0xffffffffu, acc[r][1], 16);
            acc[r][0] = add2(acc[r][0], o0);
            acc[r][1] = add2(acc[r][1], o1);
        }
        if (lane < 16) {
            #pragma unroll
            for (int r = 0; r < 12; ++r) {
                ulonglong2 v; v.x = acc[r][0]; v.y = acc[r][1];
                *(ulonglong2*)(red_s + ((w * 12 + r) << 6) + b4) = v;
            }
        }
        __syncthreads();   // sync1: red_s ready

        // epilogue: one (batch eb, col jj) per thread
        float hr = 0.f, hz = 0.f, hn = 0.f;
        #pragma unroll
        for (int ww = 0; ww < 8; ++ww) {
            const float* rb = red_s + ((ww * 12 + jj) << 6) + eb;
            hr += rb[0];
            hz += rb[4 << 6];
            hn += rb[8 << 6];
        }
        hr += bhr; hz += bhz; hn += bhn;
        float rg = 1.f / (1.f + __expf(-(xr + hr)));
        float zg = 1.f / (1.f + __expf(-(xz + hz)));
        float ng = tanhf(xn + rg * hn);
        float hnew = (1.f - zg) * ng + zg * h_prev;
        h_prev = hnew;

        // publish h into the other buffer — the ONLY store on the critical path
        asm volatile("st.global.cg.f32 [%0], %1;"
                     :: "l"(g_h[(t + 1) & 1] + col * BB + eb), "f"(hnew) : "memory");
        if (phase == 1) pool_s[tid] = hnew;

        __syncthreads();   // sync2: h stores + pool_s done, red_s consumed
        flag_publish(base + 2 + t);

        // ---- off-critical-path work, overlapped with other CTAs' progress ----
        if (phase == 0) {
            g_ys0[((size_t)t * BB + eb) * HH + col] = hnew;
        } else if (tid < 4) {
            float s = 0.f;
            #pragma unroll
            for (int b2 = 0; b2 < 64; ++b2) s += pool_s[b2 * 4 + tid];
            g_pooled[t * HH + j0 + tid] = s * (1.0f / 64.0f);
        }
        if (t + 1 < TT) {
            const float* xrow = g_xp + ((size_t)(t + 1) * BB + eb) * G3H + col;
            xr = ldg_f32(xrow);
            xz = ldg_f32(xrow + HH);
            xn = ldg_f32(xrow + 2 * HH);
            if (w == 0) flag_wait_warp0(base + 2 + t);
            __syncthreads();   // sync3: all CTAs' h visible; also protects pool_s
        }
    }
}

// ---------------- pooled @ fc_W^T + fc_b ----------------
__global__ void fc_kernel(const float* __restrict__ Wf, const float* __restrict__ bf,
                          float* __restrict__ out)
{
    int t = blockIdx.x;
    int l = threadIdx.x >> 5;
    int lane = threadIdx.x & 31;
    if (l >= LL) return;
    const float* p = g_pooled + t * HH;
    const float* w = Wf + l * HH;
    float s = 0.f;
    for (int k = lane; k < HH; k += 32) s += p[k] * w[k];
    #pragma unroll
    for (int o = 16; o > 0; o >>= 1) s += __shfl_down_sync(0xffffffffu, s, o);
    if (lane == 0) out[t * LL + l] = s + bf[l];
}

// ---------------- launcher ----------------
extern "C" void kernel_launch(void* const* d_in, const int* in_sizes, int n_in,
                              void* d_out, int out_size) {
    const int*   texts = (const int*)d_in[0];
    const float* emb   = (const float*)d_in[1];
    const float* Wih0  = (const float*)d_in[2];
    const float* Whh0  = (const float*)d_in[3];
    const float* bih0  = (const float*)d_in[4];
    const float* bhh0  = (const float*)d_in[5];
    const float* Wih1  = (const float*)d_in[6];
    const float* Whh1  = (const float*)d_in[7];
    const float* bih1  = (const float*)d_in[8];
    const float* bhh1  = (const float*)d_in[9];
    const float* fcW   = (const float*)d_in[10];
    const float* fcb   = (const float*)d_in[11];
    float* out = (float*)d_out;

    (void)cudaFuncSetAttribute(gru_layer_kernel,
                               cudaFuncAttributeMaxDynamicSharedMemorySize, GRU_SMEM_BYTES);

    dim3 gemm_grid(G3H / 64, (TT * BB) / 128);

    sgemm_bias_kernel<<<gemm_grid, 256>>>(emb, texts, Wih0, bih0, EE, 1);
    gru_layer_kernel<<<NCTA, 256, GRU_SMEM_BYTES>>>(Whh0, bhh0, 0);
    sgemm_bias_kernel<<<gemm_grid, 256>>>(emb, texts, Wih1, bih1, HH, 0);
    gru_layer_kernel<<<NCTA, 256, GRU_SMEM_BYTES>>>(Whh1, bhh1, 1);
    fc_kernel<<<TT, 32 * LL>>>(fcW, fcb, out);
}

// round 14
// speedup vs baseline: 1.0467x; 1.0467x over previous
#include <cuda_runtime.h>
#include <cstdint>

#define TT 512
#define BB 64
#define EE 300
#define HH 512
#define LL 5
#define G3H 1536
#define NCTA 128

typedef unsigned long long u64;

// ---------------- static device scratch ----------------
__device__ float g_xp[(size_t)TT * BB * G3H];   // input projections (reused both layers)
__device__ float g_ys0[(size_t)TT * BB * HH];   // layer-0 outputs
__device__ float g_h[2][HH * BB];               // double-buffered recurrent state, k-major [H][B]
__device__ float g_pooled[TT * HH];
__device__ __align__(512) unsigned int g_flags[NCTA];   // per-CTA step flags (all equal at kernel boundaries)

// ---------------- packed f32x2 helpers ----------------
__device__ __forceinline__ void fma2(u64& d, u64 a, u64 b) {
    asm("fma.rn.f32x2 %0, %1, %2, %0;" : "+l"(d) : "l"(a), "l"(b));
}
__device__ __forceinline__ u64 pack2(float x, float y) {
    u64 v; asm("mov.b64 %0, {%1, %2};" : "=l"(v) : "f"(x), "f"(y)); return v;
}
__device__ __forceinline__ float2 unpack2(u64 v) {
    float2 r; asm("mov.b64 {%0, %1}, %2;" : "=f"(r.x), "=f"(r.y) : "l"(v)); return r;
}
__device__ __forceinline__ u64 add2(u64 a, u64 b) {
    u64 d; asm("add.rn.f32x2 %0, %1, %2;" : "=l"(d) : "l"(a), "l"(b)); return d;
}
__device__ __forceinline__ void ldcg_pair(const float* p, u64& a, u64& b) {
    asm volatile("ld.global.cg.v2.u64 {%0, %1}, [%2];" : "=l"(a), "=l"(b) : "l"(p));
}
__device__ __forceinline__ float ldg_f32(const float* p) {
    float v; asm volatile("ld.global.f32 %0, [%1];" : "=f"(v) : "l"(p)); return v;
}

// ---------------- flag barrier primitives ----------------
// Publish: (all h stores) -> __syncthreads() -> thread 0 does st.release of its slot.
__device__ __forceinline__ void flag_publish(unsigned gen) {
    if (threadIdx.x == 0) {
        asm volatile("st.release.gpu.global.u32 [%0], %1;"
                     :: "l"(g_flags + blockIdx.x), "r"(gen) : "memory");
    }
}
// Wait: warp 0 only; each lane acquires 4 flags; exits when all 128 >= target.
__device__ __forceinline__ void flag_wait_warp0(unsigned target) {
    const int lane = threadIdx.x & 31;
    const unsigned* f = g_flags + lane;
    for (;;) {
        unsigned v0, v1, v2, v3;
        asm volatile("ld.acquire.gpu.global.u32 %0, [%1];" : "=r"(v0) : "l"(f)       : "memory");
        asm volatile("ld.acquire.gpu.global.u32 %0, [%1];" : "=r"(v1) : "l"(f + 32)  : "memory");
        asm volatile("ld.acquire.gpu.global.u32 %0, [%1];" : "=r"(v2) : "l"(f + 64)  : "memory");
        asm volatile("ld.acquire.gpu.global.u32 %0, [%1];" : "=r"(v3) : "l"(f + 96)  : "memory");
        bool ok = ((int)(v0 - target) >= 0) & ((int)(v1 - target) >= 0) &
                  ((int)(v2 - target) >= 0) & ((int)(v3 - target) >= 0);
        if (__all_sync(0xffffffffu, ok)) break;
    }
}

// ---------------- SGEMM with bias (unchanged) ----------------
__global__ void __launch_bounds__(256) sgemm_bias_kernel(
    const float* __restrict__ Aemb, const int* __restrict__ idx,
    const float* __restrict__ W, const float* __restrict__ bias,
    int K, int gather)
{
    __shared__ float As[16][132];
    __shared__ u64   Bs[16][66];

    const int tid = threadIdx.x;
    const int m0 = blockIdx.y * 128;
    const int n0 = blockIdx.x * 64;

    const int arow_l = tid >> 1;
    const int ak8 = (tid & 1) * 8;
    const int m = m0 + arow_l;
    const float* arow;
    if (gather) arow = Aemb + (size_t)idx[m] * K;
    else        arow = g_ys0 + (size_t)m * K;

    const int brow_l = tid >> 2;
    const int bk4 = (tid & 3) * 4;
    const float* brow = W + (size_t)(n0 + brow_l) * K;

    const int tx = tid & 15;
    const int ty = tid >> 4;

    u64 c[4][4];
    #pragma unroll
    for (int i = 0; i < 4; i++)
        #pragma unroll
        for (int j = 0; j < 4; j++) c[i][j] = 0ull;

    for (int k0 = 0; k0 < K; k0 += 16) {
        float va[8];
        if (k0 + ak8 + 7 < K) {
            float4 v0 = *(const float4*)(arow + k0 + ak8);
            float4 v1 = *(const float4*)(arow + k0 + ak8 + 4);
            va[0]=v0.x; va[1]=v0.y; va[2]=v0.z; va[3]=v0.w;
            va[4]=v1.x; va[5]=v1.y; va[6]=v1.z; va[7]=v1.w;
        } else {
            #pragma unroll
            for (int i = 0; i < 8; i++) va[i] = (k0 + ak8 + i < K) ? arow[k0 + ak8 + i] : 0.f;
        }
        float vb[4];
        if (k0 + bk4 + 3 < K) {
            float4 v = *(const float4*)(brow + k0 + bk4);
            vb[0]=v.x; vb[1]=v.y; vb[2]=v.z; vb[3]=v.w;
        } else {
            #pragma unroll
            for (int i = 0; i < 4; i++) vb[i] = (k0 + bk4 + i < K) ? brow[k0 + bk4 + i] : 0.f;
        }
        __syncthreads();
        #pragma unroll
        for (int i = 0; i < 8; i++) As[ak8 + i][arow_l] = va[i];
        #pragma unroll
        for (int i = 0; i < 4; i++) Bs[bk4 + i][brow_l] = pack2(vb[i], vb[i]);
        __syncthreads();

        #pragma unroll
        for (int k = 0; k < 16; k++) {
            ulonglong2 a01 = *(const ulonglong2*)&As[k][ty * 8];
            ulonglong2 a23 = *(const ulonglong2*)&As[k][ty * 8 + 4];
            ulonglong2 b01 = *(const ulonglong2*)&Bs[k][tx * 4];
            ulonglong2 b23 = *(const ulonglong2*)&Bs[k][tx * 4 + 2];
            u64 a[4] = {a01.x, a01.y, a23.x, a23.y};
            u64 b[4] = {b01.x, b01.y, b23.x, b23.y};
            #pragma unroll
            for (int mp = 0; mp < 4; mp++)
                #pragma unroll
                for (int n = 0; n < 4; n++) fma2(c[mp][n], a[mp], b[n]);
        }
    }

    float4 bv = *(const float4*)(bias + n0 + tx * 4);
    #pragma unroll
    for (int mp = 0; mp < 4; mp++) {
        float2 v0 = unpack2(c[mp][0]);
        float2 v1 = unpack2(c[mp][1]);
        float2 v2 = unpack2(c[mp][2]);
        float2 v3 = unpack2(c[mp][3]);
        int mlo = m0 + ty * 8 + mp * 2;
        float4 lo = {v0.x + bv.x, v1.x + bv.y, v2.x + bv.z, v3.x + bv.w};
        float4 hi = {v0.y + bv.x, v1.y + bv.y, v2.y + bv.z, v3.y + bv.w};
        *(float4*)(g_xp + (size_t)mlo * G3H + n0 + tx * 4) = lo;
        *(float4*)(g_xp + (size_t)(mlo + 1) * G3H + n0 + tx * 4) = hi;
    }
}

// ---------------- persistent GRU layer kernel (v3: flag barrier, depth-3 prefetch) ----------------
#define W_SMEM_F   (HH * 12)          // 6144 floats
#define RED_SMEM_F (8 * 12 * 64)      // 6144 floats
#define GRU_SMEM_BYTES ((W_SMEM_F + RED_SMEM_F + 256) * 4)   // 50176 B

__global__ void __launch_bounds__(256, 1) gru_layer_kernel(
    const float* __restrict__ Whh, const float* __restrict__ bhh, int phase)
{
    extern __shared__ float smem_dyn[];
    float* w_s    = smem_dyn;                 // [k:512][r:12], r = g*4 + jj
    float* red_s  = w_s + W_SMEM_F;           // [warp:8][r:12][batch:64]
    float* pool_s = red_s + RED_SMEM_F;       // [256]

    const int tid = threadIdx.x;
    const int j0 = blockIdx.x * 4;

    // invariant: all flags equal at kernel entry; own slot gives the base.
    const unsigned base = g_flags[blockIdx.x];

    // stage Whh slice (coalesced)
    for (int i = tid; i < HH * 12; i += 256) {
        int r = i >> 9, k = i & 511;          // r = g*4 + jj
        int g = r >> 2, jj = r & 3;
        w_s[k * 12 + r] = Whh[(size_t)(g * HH + j0 + jj) * HH + k];
    }
    // zero h buffer 0 (this CTA's 4 columns)
    g_h[0][blockIdx.x * 256 + tid] = 0.f;

    const int w    = tid >> 5;
    const int lane = tid & 31;
    const int kpar = lane >> 4;
    const int b4   = (lane & 15) * 4;
    const int eb   = tid >> 2;
    const int jj   = tid & 3;
    const int col  = j0 + jj;

    const float bhr = bhh[col], bhz = bhh[HH + col], bhn = bhh[2 * HH + col];
    float h_prev = 0.f;

    const float* wk_base = w_s + (w * 64 + kpar) * 12;
    const size_t h_off   = (size_t)(w * 64 + kpar) * BB + b4;

    // prefetch xp for t=0 (independent of barrier)
    const float* xrow0 = g_xp + (size_t)eb * G3H + col;
    float xr = ldg_f32(xrow0);
    float xz = ldg_f32(xrow0 + HH);
    float xn = ldg_f32(xrow0 + 2 * HH);

    // init barrier
    __syncthreads();
    flag_publish(base + 1);
    if (w == 0) flag_wait_warp0(base + 1);
    __syncthreads();

    for (int t = 0; t < TT; ++t) {
        const float* hp = g_h[t & 1] + h_off;

        u64 acc[12][2];
        #pragma unroll
        for (int r = 0; r < 12; ++r) { acc[r][0] = 0ull; acc[r][1] = 0ull; }

        // depth-3 pipelined GEMV over 32 iterations (2 k each)
        u64 hb[4][2];
        ldcg_pair(hp,       hb[0][0], hb[0][1]);
        ldcg_pair(hp + 128, hb[1][0], hb[1][1]);
        ldcg_pair(hp + 256, hb[2][0], hb[2][1]);
        float4 wA0 = *(const float4*)(wk_base);
        float4 wA1 = *(const float4*)(wk_base + 4);
        float4 wA2 = *(const float4*)(wk_base + 8);

        #pragma unroll 4
        for (int i = 0; i < 32; ++i) {
            if (i + 3 < 32)
                ldcg_pair(hp + (size_t)(i + 3) * 128, hb[(i + 3) & 3][0], hb[(i + 3) & 3][1]);
            float4 wB0, wB1, wB2;
            if (i + 1 < 32) {
                const float* wn = wk_base + (i + 1) * 24;
                wB0 = *(const float4*)(wn);
                wB1 = *(const float4*)(wn + 4);
                wB2 = *(const float4*)(wn + 8);
            }
            u64 h0 = hb[i & 3][0], h1 = hb[i & 3][1];
            float wf[12] = {wA0.x, wA0.y, wA0.z, wA0.w,
                            wA1.x, wA1.y, wA1.z, wA1.w,
                            wA2.x, wA2.y, wA2.z, wA2.w};
            #pragma unroll
            for (int r = 0; r < 12; ++r) {
                u64 wp = pack2(wf[r], wf[r]);
                fma2(acc[r][0], h0, wp);
                fma2(acc[r][1], h1, wp);
            }
            wA0 = wB0; wA1 = wB1; wA2 = wB2;
        }

        // fold odd-k half into even half
        #pragma unroll
        for (int r = 0; r < 12; ++r) {
            u64 o0 = __shfl_down_sync(0xffffffffu, acc[r][0], 16);
            u64 o1 = __shfl_down_sync(0xffffffffu, acc[r][1], 16);
            acc[r][0] = add2(acc[r][0], o0);
            acc[r][1] = add2(acc[r][1], o1);
        }
        if (lane < 16) {
            #pragma unroll
            for (int r = 0; r < 12; ++r) {
                ulonglong2 v; v.x = acc[r][0]; v.y = acc[r][1];
                *(ulonglong2*)(red_s + ((w * 12 + r) << 6) + b4) = v;
            }
        }
        __syncthreads();   // sync1: red_s ready

        // epilogue: one (batch eb, col jj) per thread
        float hr = 0.f, hz = 0.f, hn = 0.f;
        #pragma unroll
        for (int ww = 0; ww < 8; ++ww) {
            const float* rb = red_s + ((ww * 12 + jj) << 6) + eb;
            hr += rb[0];
            hz += rb[4 << 6];
            hn += rb[8 << 6];
        }
        hr += bhr; hz += bhz; hn += bhn;
        float rg = 1.f / (1.f + __expf(-(xr + hr)));
        float zg = 1.f / (1.f + __expf(-(xz + hz)));
        float ng = tanhf(xn + rg * hn);
        float hnew = (1.f - zg) * ng + zg * h_prev;
        h_prev = hnew;

        // publish h into the other buffer — the ONLY store on the critical path
        asm volatile("st.global.cg.f32 [%0], %1;"
                     :: "l"(g_h[(t + 1) & 1] + col * BB + eb), "f"(hnew) : "memory");
        if (phase == 1) pool_s[tid] = hnew;

        __syncthreads();   // sync2: h stores + pool_s done, red_s consumed
        flag_publish(base + 2 + t);

        // ---- off-critical-path work, overlapped with other CTAs' progress ----
        if (phase == 0) {
            g_ys0[((size_t)t * BB + eb) * HH + col] = hnew;
        } else if (tid < 4) {
            float s = 0.f;
            #pragma unroll
            for (int b2 = 0; b2 < 64; ++b2) s += pool_s[b2 * 4 + tid];
            g_pooled[t * HH + j0 + tid] = s * (1.0f / 64.0f);
        }
        if (t + 1 < TT) {
            const float* xrow = g_xp + ((size_t)(t + 1) * BB + eb) * G3H + col;
            xr = ldg_f32(xrow);
            xz = ldg_f32(xrow + HH);
            xn = ldg_f32(xrow + 2 * HH);
            if (w == 0) flag_wait_warp0(base + 2 + t);
            __syncthreads();   // sync3: all CTAs' h visible; also protects pool_s
        }
    }
}

// ---------------- pooled @ fc_W^T + fc_b ----------------
__global__ void fc_kernel(const float* __restrict__ Wf, const float* __restrict__ bf,
                          float* __restrict__ out)
{
    int t = blockIdx.x;
    int l = threadIdx.x >> 5;
    int lane = threadIdx.x & 31;
    if (l >= LL) return;
    const float* p = g_pooled + t * HH;
    const float* w = Wf + l * HH;
    float s = 0.f;
    for (int k = lane; k < HH; k += 32) s += p[k] * w[k];
    #pragma unroll
    for (int o = 16; o > 0; o >>= 1) s += __shfl_down_sync(0xffffffffu, s, o);
    if (lane == 0) out[t * LL + l] = s + bf[l];
}

// ---------------- launcher ----------------
extern "C" void kernel_launch(void* const* d_in, const int* in_sizes, int n_in,
                              void* d_out, int out_size) {
    const int*   texts = (const int*)d_in[0];
    const float* emb   = (const float*)d_in[1];
    const float* Wih0  = (const float*)d_in[2];
    const float* Whh0  = (const float*)d_in[3];
    const float* bih0  = (const float*)d_in[4];
    const float* bhh0  = (const float*)d_in[5];
    const float* Wih1  = (const float*)d_in[6];
    const float* Whh1  = (const float*)d_in[7];
    const float* bih1  = (const float*)d_in[8];
    const float* bhh1  = (const float*)d_in[9];
    const float* fcW   = (const float*)d_in[10];
    const float* fcb   = (const float*)d_in[11];
    float* out = (float*)d_out;

    (void)cudaFuncSetAttribute(gru_layer_kernel,
                               cudaFuncAttributeMaxDynamicSharedMemorySize, GRU_SMEM_BYTES);

    dim3 gemm_grid(G3H / 64, (TT * BB) / 128);

    sgemm_bias_kernel<<<gemm_grid, 256>>>(emb, texts, Wih0, bih0, EE, 1);
    gru_layer_kernel<<<NCTA, 256, GRU_SMEM_BYTES>>>(Whh0, bhh0, 0);
    sgemm_bias_kernel<<<gemm_grid, 256>>>(emb, texts, Wih1, bih1, HH, 0);
    gru_layer_kernel<<<NCTA, 256, GRU_SMEM_BYTES>>>(Whh1, bhh1, 1);
    fc_kernel<<<TT, 32 * LL>>>(fcW, fcb, out);
}